// round 8
// baseline (speedup 1.0000x reference)
#include <cuda_runtime.h>
#include <cuda_fp16.h>
#include <cuda_bf16.h>
#include <cstdint>

#define N_NODES 100000
#define N_EDGES 3200000
#define IN_K    512     // IN_DIM * N_SEQ
#define HID1    256
#define HID2    128
#define ENDD    64

// ---------------- scratch (device globals; no allocation allowed) ----------------
__device__ int    g_deg_out[N_NODES];
__device__ int    g_deg_in[N_NODES];
__device__ int    g_fill[N_NODES];
__device__ float  g_rso[N_NODES];
__device__ float  g_rsi[N_NODES];
__device__ int    g_rowptr[N_NODES + 1];
__device__ int    g_bsums[512];
__device__ int    g_colidx[N_EDGES];
__device__ __half g_W1t[HID1 * IN_K];             // W1 transposed fp16 [n=256][k=512]
__device__ __half g_Z1h[(size_t)N_NODES * HID1];  // 51 MB (UNscaled X@W1)
__device__ __half g_A1h[(size_t)N_NODES * HID1];  // 51 MB
__device__ __half g_Z2h[(size_t)N_NODES * ENDD];  // 12.8 MB
__device__ __half g_W2ft[ENDD * HID1];            // (W2@Wo1)^T fp16 [n=64][k=256]
__device__ float  g_bh[ENDD];                     // b2 @ Wo1 + bo1

// ---------------- preprocessing kernels ----------------
__global__ void k_cvtW1(const float* __restrict__ W1)
{
    int i = blockIdx.x * blockDim.x + threadIdx.x;
    if (i < HID1 * IN_K) {
        int n = i >> 9;
        int k = i & 511;
        g_W1t[i] = __float2half(W1[k * HID1 + n]);
    }
}

__global__ void k_zero()
{
    int i = blockIdx.x * blockDim.x + threadIdx.x;
    if (i < N_NODES) { g_deg_out[i] = 0; g_deg_in[i] = 0; g_fill[i] = 0; }
}

__global__ void k_degree(const int* __restrict__ src, const int* __restrict__ dst)
{
    int e = blockIdx.x * blockDim.x + threadIdx.x;
    if (e < N_EDGES) {
        atomicAdd(&g_deg_out[src[e]], 1);
        atomicAdd(&g_deg_in[dst[e]], 1);
    }
}

__global__ void k_rsqrt()
{
    int i = blockIdx.x * blockDim.x + threadIdx.x;
    if (i < N_NODES) {
        g_rso[i] = rsqrtf((float)max(g_deg_out[i], 1));
        g_rsi[i] = rsqrtf((float)max(g_deg_in[i], 1));
    }
}

__global__ void k_scan1()
{
    __shared__ int s[256];
    int t = threadIdx.x;
    int i = blockIdx.x * 256 + t;
    int v = (i < N_NODES) ? g_deg_in[i] : 0;
    s[t] = v; __syncthreads();
    #pragma unroll
    for (int off = 1; off < 256; off <<= 1) {
        int u = (t >= off) ? s[t - off] : 0;
        __syncthreads();
        s[t] += u;
        __syncthreads();
    }
    if (i < N_NODES) g_rowptr[i] = s[t] - v;
    if (t == 255) g_bsums[blockIdx.x] = s[255];
}

__global__ void k_scan2()
{
    __shared__ int s[512];
    const int nb = (N_NODES + 255) / 256;   // 391
    int t = threadIdx.x;
    int v = (t < nb) ? g_bsums[t] : 0;
    s[t] = v; __syncthreads();
    #pragma unroll
    for (int off = 1; off < 512; off <<= 1) {
        int u = (t >= off) ? s[t - off] : 0;
        __syncthreads();
        s[t] += u;
        __syncthreads();
    }
    if (t < nb) g_bsums[t] = s[t] - v;
}

__global__ void k_scan3()
{
    int i = blockIdx.x * blockDim.x + threadIdx.x;
    if (i < N_NODES) g_rowptr[i] += g_bsums[i >> 8];
    if (i == 0) g_rowptr[N_NODES] = N_EDGES;
}

__global__ void k_fill(const int* __restrict__ src, const int* __restrict__ dst)
{
    int e = blockIdx.x * blockDim.x + threadIdx.x;
    if (e < N_EDGES) {
        int d = dst[e];
        int p = g_rowptr[d] + atomicAdd(&g_fill[d], 1);
        g_colidx[p] = src[e];
    }
}

__global__ void k_fuse(const float* __restrict__ W2, const float* __restrict__ Wo1,
                       const float* __restrict__ b2, const float* __restrict__ bo1)
{
    int j = threadIdx.x;   // 0..63
    int k = blockIdx.x;    // 0..256
    if (k < HID1) {
        float s = 0.f;
        #pragma unroll 8
        for (int m = 0; m < HID2; m++) s += W2[k * HID2 + m] * Wo1[m * ENDD + j];
        g_W2ft[j * HID1 + k] = __float2half(s);
    } else {
        float s = bo1[j];
        #pragma unroll 8
        for (int m = 0; m < HID2; m++) s += b2[m] * Wo1[m * ENDD + j];
        g_bh[j] = s;
    }
}

// ---------------- fp16 HMMA helpers ----------------
__device__ __forceinline__ void mma_f16(float* c, uint32_t a0, uint32_t a1,
                                        uint32_t a2, uint32_t a3,
                                        uint32_t b0, uint32_t b1)
{
    asm volatile(
        "mma.sync.aligned.m16n8k16.row.col.f32.f16.f16.f32 "
        "{%0,%1,%2,%3}, {%4,%5,%6,%7}, {%8,%9}, {%0,%1,%2,%3};\n"
        : "+f"(c[0]), "+f"(c[1]), "+f"(c[2]), "+f"(c[3])
        : "r"(a0), "r"(a1), "r"(a2), "r"(a3), "r"(b0), "r"(b1));
}

__device__ __forceinline__ void ldsm_x4(uint32_t& r0, uint32_t& r1, uint32_t& r2,
                                        uint32_t& r3, uint32_t addr)
{
    asm volatile("ldmatrix.sync.aligned.m8n8.x4.shared.b16 {%0,%1,%2,%3}, [%4];"
                 : "=r"(r0), "=r"(r1), "=r"(r2), "=r"(r3) : "r"(addr));
}

#define HPITCH 40
#define STAGES 3

__device__ __forceinline__ uint32_t lds_h2(const __half* p)
{
    return *reinterpret_cast<const uint32_t*>(p);
}

// ---------------- GEMM1: Z1h = X @ W1 (UNscaled), fp16 HMMA ----------------
// BM=128 BN=256 BK=32; 512 threads = 16 warps (2 m x 8 n); warp tile 64x32.
// A read exactly once from DRAM. 3-stage ring, ldmatrix fragments.
__global__ void __launch_bounds__(512, 1)
gemm1_h(const float* __restrict__ A, __half* __restrict__ C)
{
    constexpr int M = N_NODES, N = HID1, K = IN_K;
    constexpr int NT = K / 32;          // 16
    constexpr int ASZ = 128 * HPITCH;   // halves per A stage
    constexpr int BSZ = 256 * HPITCH;   // halves per B stage

    extern __shared__ __half smh[];
    __half* Asb = smh;                  // [STAGES][128][HPITCH]
    __half* Bsb = smh + STAGES * ASZ;   // [STAGES][256][HPITCH]

    const int tid = threadIdx.x;
    const int lane = tid & 31;
    const int wid = tid >> 5;
    const int warp_m = wid >> 3;        // 0..1
    const int warp_n = wid & 7;         // 0..7
    const int g  = lane >> 2;
    const int tc = lane & 3;
    const int blockRow = blockIdx.x * 128;

    float acc[4][4][4];
    #pragma unroll
    for (int i = 0; i < 4; i++)
        #pragma unroll
        for (int j = 0; j < 4; j++)
            #pragma unroll
            for (int q = 0; q < 4; q++) acc[i][j][q] = 0.f;

    // A staging: 2 float4 per thread per tile (128 rows x 32 k fp32)
    int a_r[2], a_c[2];
    #pragma unroll
    for (int i = 0; i < 2; i++) {
        int slot = tid + i * 512;       // 0..1023
        a_r[i] = slot >> 3;             // 0..127
        a_c[i] = (slot & 7) * 4;        // 0..28
    }
    // B: 2 cp.async 16B per thread per tile (256 n x 32 k half)
    int b_n[2], b_c[2];
    #pragma unroll
    for (int i = 0; i < 2; i++) {
        int id = tid + i * 512;         // 0..1023
        b_n[i] = id >> 2;               // 0..255
        b_c[i] = (id & 3) * 8;          // 0..24
    }

    const int a_ld_r = (lane & 7) + ((lane >> 3) & 1) * 8;
    const int a_ld_c = (lane >> 4) * 8;
    const int b_ld_n = (lane & 7) + ((lane >> 4) & 1) * 8;
    const int b_ld_c = ((lane >> 3) & 1) * 8;

    float4 Areg[2];

    auto ldg_A = [&](int k0) {
        #pragma unroll
        for (int i = 0; i < 2; i++) {
            int grow = blockRow + a_r[i];
            Areg[i] = (grow < M) ? *(const float4*)(A + (size_t)grow * K + k0 + a_c[i])
                                 : make_float4(0.f, 0.f, 0.f, 0.f);
        }
    };
    auto sts_A = [&](int stage) {
        __half* asb = Asb + stage * ASZ;
        #pragma unroll
        for (int i = 0; i < 2; i++) {
            __half2 h0 = __floats2half2_rn(Areg[i].x, Areg[i].y);
            __half2 h1 = __floats2half2_rn(Areg[i].z, Areg[i].w);
            uint2 u;
            u.x = *reinterpret_cast<uint32_t*>(&h0);
            u.y = *reinterpret_cast<uint32_t*>(&h1);
            *(uint2*)&asb[a_r[i] * HPITCH + a_c[i]] = u;
        }
    };
    auto cp_B = [&](int stage, int k0) {
        __half* bsb = Bsb + stage * BSZ;
        #pragma unroll
        for (int i = 0; i < 2; i++) {
            uint32_t dst = (uint32_t)__cvta_generic_to_shared(&bsb[b_n[i] * HPITCH + b_c[i]]);
            const __half* srcp = g_W1t + (size_t)b_n[i] * K + k0 + b_c[i];
            asm volatile("cp.async.cg.shared.global [%0], [%1], 16;\n"
                         :: "r"(dst), "l"(srcp));
        }
        asm volatile("cp.async.commit_group;\n");
    };

    // prologue
    ldg_A(0);
    sts_A(0);
    cp_B(0, 0);
    ldg_A(32);
    cp_B(1, 32);

    for (int kt = 0; kt < NT; kt++) {
        if (kt + 1 < NT) asm volatile("cp.async.wait_group 1;\n");
        else             asm volatile("cp.async.wait_group 0;\n");
        __syncthreads();

        if (kt + 1 < NT) sts_A((kt + 1) % STAGES);
        if (kt + 2 < NT) { ldg_A((kt + 2) * 32); cp_B((kt + 2) % STAGES, (kt + 2) * 32); }

        const __half* asb = Asb + (kt % STAGES) * ASZ;
        const __half* bsb = Bsb + (kt % STAGES) * BSZ;

        #pragma unroll
        for (int ks = 0; ks < 2; ks++) {
            const int kb = ks * 16;
            uint32_t af[4][4];
            #pragma unroll
            for (int mt = 0; mt < 4; mt++) {
                int row = warp_m * 64 + mt * 16 + a_ld_r;
                uint32_t addr = (uint32_t)__cvta_generic_to_shared(
                    &asb[row * HPITCH + kb + a_ld_c]);
                ldsm_x4(af[mt][0], af[mt][1], af[mt][2], af[mt][3], addr);
            }
            uint32_t bf[4][2];
            #pragma unroll
            for (int h = 0; h < 2; h++) {
                int n = warp_n * 32 + h * 16 + b_ld_n;
                uint32_t addr = (uint32_t)__cvta_generic_to_shared(
                    &bsb[n * HPITCH + kb + b_ld_c]);
                ldsm_x4(bf[2 * h][0], bf[2 * h][1], bf[2 * h + 1][0], bf[2 * h + 1][1], addr);
            }
            #pragma unroll
            for (int mt = 0; mt < 4; mt++)
                #pragma unroll
                for (int nt = 0; nt < 4; nt++)
                    mma_f16(acc[mt][nt], af[mt][0], af[mt][1], af[mt][2], af[mt][3],
                            bf[nt][0], bf[nt][1]);
        }
    }

    // epilogue: plain half2 store (no rowscale — applied in agg1)
    #pragma unroll
    for (int mt = 0; mt < 4; mt++) {
        int row0 = blockRow + warp_m * 64 + mt * 16 + g;
        int row1 = row0 + 8;
        #pragma unroll
        for (int nt = 0; nt < 4; nt++) {
            int col = warp_n * 32 + nt * 8 + tc * 2;
            if (row0 < M)
                *(__half2*)(C + (size_t)row0 * N + col) =
                    __floats2half2_rn(acc[mt][nt][0], acc[mt][nt][1]);
            if (row1 < M)
                *(__half2*)(C + (size_t)row1 * N + col) =
                    __floats2half2_rn(acc[mt][nt][2], acc[mt][nt][3]);
        }
    }
}

// ---------------- GEMM2: Z2h = rso * (A1h @ W2f), fp16 HMMA ----------------
__global__ void __launch_bounds__(256, 2)
gemm2_h(const __half* __restrict__ A, const float* __restrict__ rowscale,
        __half* __restrict__ C)
{
    constexpr int M = N_NODES, N = ENDD, K = HID1;
    constexpr int NT = K / 32;   // 8

    __shared__ __half As[2][128][HPITCH];
    __shared__ __half Bs[2][64][HPITCH];

    const int tid = threadIdx.x;
    const int lane = tid & 31;
    const int wid = tid >> 5;
    const int warp_m = wid >> 1;
    const int warp_n = wid & 1;
    const int g  = lane >> 2;
    const int tc = lane & 3;
    const int blockRow = blockIdx.y * 128;

    float acc[2][4][4];
    #pragma unroll
    for (int i = 0; i < 2; i++)
        #pragma unroll
        for (int j = 0; j < 4; j++)
            #pragma unroll
            for (int q = 0; q < 4; q++) acc[i][j][q] = 0.f;

    int a_r[2], a_c[2];
    #pragma unroll
    for (int i = 0; i < 2; i++) {
        int id = tid + i * 256;
        a_r[i] = id >> 2;
        a_c[i] = (id & 3) * 8;
    }
    const int bn = tid >> 2;
    const int bc = (tid & 3) * 8;

    auto cp_AB = [&](int stage, int k0) {
        #pragma unroll
        for (int i = 0; i < 2; i++) {
            uint32_t dst = (uint32_t)__cvta_generic_to_shared(&As[stage][a_r[i]][a_c[i]]);
            const __half* srcp = A + (size_t)(blockRow + a_r[i]) * K + k0 + a_c[i];
            int sz = (blockRow + a_r[i] < M) ? 16 : 0;
            asm volatile("cp.async.cg.shared.global [%0], [%1], 16, %2;\n"
                         :: "r"(dst), "l"(srcp), "r"(sz));
        }
        {
            uint32_t dst = (uint32_t)__cvta_generic_to_shared(&Bs[stage][bn][bc]);
            const __half* srcp = g_W2ft + (size_t)bn * K + k0 + bc;
            asm volatile("cp.async.cg.shared.global [%0], [%1], 16;\n"
                         :: "r"(dst), "l"(srcp));
        }
        asm volatile("cp.async.commit_group;\n");
    };

    cp_AB(0, 0);

    for (int kt = 0; kt < NT; kt++) {
        asm volatile("cp.async.wait_group 0;\n");
        __syncthreads();
        if (kt + 1 < NT) cp_AB((kt + 1) & 1, (kt + 1) * 32);

        const int st = kt & 1;
        #pragma unroll
        for (int ks = 0; ks < 2; ks++) {
            const int kb = ks * 16;
            uint32_t af[2][4];
            #pragma unroll
            for (int mt = 0; mt < 2; mt++) {
                int row = warp_m * 32 + mt * 16 + g;
                af[mt][0] = lds_h2(&As[st][row    ][kb + 2 * tc    ]);
                af[mt][1] = lds_h2(&As[st][row + 8][kb + 2 * tc    ]);
                af[mt][2] = lds_h2(&As[st][row    ][kb + 2 * tc + 8]);
                af[mt][3] = lds_h2(&As[st][row + 8][kb + 2 * tc + 8]);
            }
            uint32_t bf[4][2];
            #pragma unroll
            for (int nt = 0; nt < 4; nt++) {
                int n = warp_n * 32 + nt * 8 + g;
                bf[nt][0] = lds_h2(&Bs[st][n][kb + 2 * tc    ]);
                bf[nt][1] = lds_h2(&Bs[st][n][kb + 2 * tc + 8]);
            }
            #pragma unroll
            for (int mt = 0; mt < 2; mt++)
                #pragma unroll
                for (int nt = 0; nt < 4; nt++)
                    mma_f16(acc[mt][nt], af[mt][0], af[mt][1], af[mt][2], af[mt][3],
                            bf[nt][0], bf[nt][1]);
        }
    }

    #pragma unroll
    for (int mt = 0; mt < 2; mt++) {
        int row0 = blockRow + warp_m * 32 + mt * 16 + g;
        int row1 = row0 + 8;
        float s0 = (row0 < M) ? rowscale[row0] : 0.f;
        float s1 = (row1 < M) ? rowscale[row1] : 0.f;
        #pragma unroll
        for (int nt = 0; nt < 4; nt++) {
            int col = warp_n * 32 + nt * 8 + tc * 2;
            if (row0 < M)
                *(__half2*)(C + (size_t)row0 * N + col) =
                    __floats2half2_rn(acc[mt][nt][0] * s0, acc[mt][nt][1] * s0);
            if (row1 < M)
                *(__half2*)(C + (size_t)row1 * N + col) =
                    __floats2half2_rn(acc[mt][nt][2] * s1, acc[mt][nt][3] * s1);
        }
    }
}

// ---------------- aggregation layer 1 (dim 256, fp16) + per-edge rso + relu ----
__global__ void k_agg1_relu(const float* __restrict__ b1)
{
    int w    = threadIdx.x >> 5;
    int lane = threadIdx.x & 31;
    int n = blockIdx.x * 8 + w;
    if (n >= N_NODES) return;
    int beg = g_rowptr[n], end = g_rowptr[n + 1];

    float acc[8];
    #pragma unroll
    for (int i = 0; i < 8; i++) acc[i] = 0.f;

    const __half* basep = g_Z1h + (lane << 3);

    #define ACC8(u, r) do { \
        float2 f0 = __half22float2(*reinterpret_cast<__half2*>(&(u).x)); \
        float2 f1 = __half22float2(*reinterpret_cast<__half2*>(&(u).y)); \
        float2 f2 = __half22float2(*reinterpret_cast<__half2*>(&(u).z)); \
        float2 f3 = __half22float2(*reinterpret_cast<__half2*>(&(u).w)); \
        acc[0] = fmaf(r, f0.x, acc[0]); acc[1] = fmaf(r, f0.y, acc[1]); \
        acc[2] = fmaf(r, f1.x, acc[2]); acc[3] = fmaf(r, f1.y, acc[3]); \
        acc[4] = fmaf(r, f2.x, acc[4]); acc[5] = fmaf(r, f2.y, acc[5]); \
        acc[6] = fmaf(r, f3.x, acc[6]); acc[7] = fmaf(r, f3.y, acc[7]); } while (0)

    int e = beg;
    for (; e + 4 <= end; e += 4) {
        int c0 = g_colidx[e], c1 = g_colidx[e + 1], c2 = g_colidx[e + 2], c3 = g_colidx[e + 3];
        float r0 = g_rso[c0], r1 = g_rso[c1], r2 = g_rso[c2], r3 = g_rso[c3];
        uint4 u0 = *(const uint4*)(basep + (size_t)c0 * HID1);
        uint4 u1 = *(const uint4*)(basep + (size_t)c1 * HID1);
        uint4 u2 = *(const uint4*)(basep + (size_t)c2 * HID1);
        uint4 u3 = *(const uint4*)(basep + (size_t)c3 * HID1);
        ACC8(u0, r0); ACC8(u1, r1); ACC8(u2, r2); ACC8(u3, r3);
    }
    for (; e < end; e++) {
        int c = g_colidx[e];
        float r = g_rso[c];
        uint4 u = *(const uint4*)(basep + (size_t)c * HID1);
        ACC8(u, r);
    }
    #undef ACC8

    float s = g_rsi[n];
    float4 bb0 = *(const float4*)(b1 + lane * 8);
    float4 bb1 = *(const float4*)(b1 + lane * 8 + 4);
    __half2 o0 = __floats2half2_rn(fmaxf(fmaf(s, acc[0], bb0.x), 0.f),
                                   fmaxf(fmaf(s, acc[1], bb0.y), 0.f));
    __half2 o1 = __floats2half2_rn(fmaxf(fmaf(s, acc[2], bb0.z), 0.f),
                                   fmaxf(fmaf(s, acc[3], bb0.w), 0.f));
    __half2 o2 = __floats2half2_rn(fmaxf(fmaf(s, acc[4], bb1.x), 0.f),
                                   fmaxf(fmaf(s, acc[5], bb1.y), 0.f));
    __half2 o3 = __floats2half2_rn(fmaxf(fmaf(s, acc[6], bb1.z), 0.f),
                                   fmaxf(fmaf(s, acc[7], bb1.w), 0.f));
    uint4 st;
    st.x = *reinterpret_cast<uint32_t*>(&o0);
    st.y = *reinterpret_cast<uint32_t*>(&o1);
    st.z = *reinterpret_cast<uint32_t*>(&o2);
    st.w = *reinterpret_cast<uint32_t*>(&o3);
    *(uint4*)(g_A1h + (size_t)n * HID1 + (lane << 3)) = st;
}

// ---------------- aggregation layer 2 (dim 64, fp16) + fused head ----------------
__global__ void k_agg2_head(const float* __restrict__ Wo2, const float* __restrict__ bo2,
                            float* __restrict__ out)
{
    int w    = threadIdx.x >> 5;
    int lane = threadIdx.x & 31;
    int n = blockIdx.x * 8 + w;
    if (n >= N_NODES) return;
    int beg = g_rowptr[n], end = g_rowptr[n + 1];

    float2 acc = make_float2(0.f, 0.f);
    int e = beg;
    for (; e + 4 <= end; e += 4) {
        int c0 = g_colidx[e], c1 = g_colidx[e + 1], c2 = g_colidx[e + 2], c3 = g_colidx[e + 3];
        float2 f0 = __half22float2(*(const __half2*)(g_Z2h + (size_t)c0 * ENDD + (lane << 1)));
        float2 f1 = __half22float2(*(const __half2*)(g_Z2h + (size_t)c1 * ENDD + (lane << 1)));
        float2 f2 = __half22float2(*(const __half2*)(g_Z2h + (size_t)c2 * ENDD + (lane << 1)));
        float2 f3 = __half22float2(*(const __half2*)(g_Z2h + (size_t)c3 * ENDD + (lane << 1)));
        acc.x += (f0.x + f1.x) + (f2.x + f3.x);
        acc.y += (f0.y + f1.y) + (f2.y + f3.y);
    }
    for (; e < end; e++) {
        int c = g_colidx[e];
        float2 f = __half22float2(*(const __half2*)(g_Z2h + (size_t)c * ENDD + (lane << 1)));
        acc.x += f.x; acc.y += f.y;
    }
    float s  = g_rsi[n];
    float t0 = fmaxf(fmaf(s, acc.x, g_bh[lane * 2 + 0]), 0.f);
    float t1 = fmaxf(fmaf(s, acc.y, g_bh[lane * 2 + 1]), 0.f);
    float p  = t0 * Wo2[lane * 2] + t1 * Wo2[lane * 2 + 1];
    #pragma unroll
    for (int off = 16; off; off >>= 1) p += __shfl_down_sync(0xffffffffu, p, off);
    if (lane == 0) out[n] = p + bo2[0];
}

// ---------------- launch ----------------
extern "C" void kernel_launch(void* const* d_in, const int* in_sizes, int n_in,
                              void* d_out, int out_size)
{
    const float* features = (const float*)d_in[0];
    const int*   src      = (const int*)d_in[1];
    const int*   dst      = (const int*)d_in[2];
    const float* W1       = (const float*)d_in[3];
    const float* b1       = (const float*)d_in[4];
    const float* W2       = (const float*)d_in[5];
    const float* b2       = (const float*)d_in[6];
    const float* Wo1      = (const float*)d_in[7];
    const float* bo1      = (const float*)d_in[8];
    const float* Wo2      = (const float*)d_in[9];
    const float* bo2      = (const float*)d_in[10];
    float* out = (float*)d_out;

    const int nodeBlocks = (N_NODES + 255) / 256;     // 391
    const int edgeBlocks = (N_EDGES + 255) / 256;     // 12500
    const int GEMM1_SMEM = STAGES * (128 + 256) * HPITCH * (int)sizeof(__half); // 92160

    static cudaStream_t s2 = nullptr;
    static cudaEvent_t  e1 = nullptr, e2 = nullptr;
    if (!s2) {
        cudaStreamCreateWithFlags(&s2, cudaStreamNonBlocking);
        cudaEventCreateWithFlags(&e1, cudaEventDisableTiming);
        cudaEventCreateWithFlags(&e2, cudaEventDisableTiming);
        cudaFuncSetAttribute(gemm1_h, cudaFuncAttributeMaxDynamicSharedMemorySize,
                             GEMM1_SMEM);
    }

    float *rso;
    __half *z1, *a1, *z2;
    cudaGetSymbolAddress((void**)&rso, g_rso);
    cudaGetSymbolAddress((void**)&z1, g_Z1h);
    cudaGetSymbolAddress((void**)&a1, g_A1h);
    cudaGetSymbolAddress((void**)&z2, g_Z2h);

    // main stream: W1 convert, then gemm1 (independent of graph preprocessing)
    k_cvtW1<<<(HID1 * IN_K + 255) / 256, 256>>>(W1);
    cudaEventRecord(e1, 0);

    // side stream: CSR/degree chain, forked after cvtW1
    cudaStreamWaitEvent(s2, e1, 0);
    k_zero<<<nodeBlocks, 256, 0, s2>>>();
    k_degree<<<edgeBlocks, 256, 0, s2>>>(src, dst);

    // launch #4 (ncu-captured): layer-1 fp16 HMMA GEMM, Z1h = X @ W1 (unscaled)
    gemm1_h<<<(N_NODES + 127) / 128, 512, GEMM1_SMEM>>>(features, z1);

    k_rsqrt<<<nodeBlocks, 256, 0, s2>>>();
    k_scan1<<<nodeBlocks, 256, 0, s2>>>();
    k_scan2<<<1, 512, 0, s2>>>();
    k_scan3<<<nodeBlocks, 256, 0, s2>>>();
    k_fill<<<edgeBlocks, 256, 0, s2>>>(src, dst);
    k_fuse<<<HID1 + 1, ENDD, 0, s2>>>(W2, Wo1, b2, bo1);
    cudaEventRecord(e2, s2);

    // join: aggregation needs CSR + rso + gemm1
    cudaStreamWaitEvent(0, e2, 0);

    // A1h = relu(rsi * sum(rso[src] * Z1h[src]) + b1)
    k_agg1_relu<<<(N_NODES + 7) / 8, 256>>>(b1);

    // layer 2 (folded): Z2h = rso * (A1h @ (W2@Wo1))
    {
        dim3 grid(1, (N_NODES + 127) / 128);
        gemm2_h<<<grid, 256>>>(a1, rso, z2);
    }
    // out = relu(rsi * agg(Z2h) + bh) @ Wo2 + bo2
    k_agg2_head<<<(N_NODES + 7) / 8, 256>>>(Wo2, bo2, out);
}